// round 13
// baseline (speedup 1.0000x reference)
#include <cuda_runtime.h>
#include <math.h>

#define H    2048
#define V    50257
#define LL   80
#define H4   (H/4)      // 512 float4 per H-length vector
#define G4H  (4*H)      // 8192 gate rows per matrix
#define GB   (G4H / 8)  // 1024 blocks per gate matrix
#define NRED 64         // partial-reduction blocks for log-softmax

// ---------------- scratch (device globals — no allocation allowed) ----------
__device__ float g_attn_logits[LL];
__device__ float g_attn_applied[H];
__device__ float g_comb_emb[H];    // emb-half partial of the combine GEMV
__device__ float g_lstm_in[H];
__device__ float g_gp[2 * G4H];    // [0,4H): W_ih partial + b_ih ; [4H,8H): W_hh partial + b_hh
__device__ float g_h_new[H];
__device__ float g_logits[V];
__device__ float g_pmax[NRED];
__device__ float g_psum[NRED];

// ---------------- streams/events (static init; no device alloc in launch) ---
static cudaStream_t g_s2, g_s3;
static cudaEvent_t  g_ev_fork, g_ev_join, g_ev_comb;
namespace {
struct StreamInit {
    StreamInit() {
        cudaStreamCreateWithFlags(&g_s2, cudaStreamNonBlocking);
        cudaStreamCreateWithFlags(&g_s3, cudaStreamNonBlocking);
        cudaEventCreateWithFlags(&g_ev_fork, cudaEventDisableTiming);
        cudaEventCreateWithFlags(&g_ev_join, cudaEventDisableTiming);
        cudaEventCreateWithFlags(&g_ev_comb, cudaEventDisableTiming);
    }
};
StreamInit g_stream_init;
}

// ---------------- helpers ----------------
__device__ __forceinline__ float warp_reduce_add(float v) {
    v += __shfl_xor_sync(0xffffffffu, v, 16);
    v += __shfl_xor_sync(0xffffffffu, v, 8);
    v += __shfl_xor_sync(0xffffffffu, v, 4);
    v += __shfl_xor_sync(0xffffffffu, v, 2);
    v += __shfl_xor_sync(0xffffffffu, v, 1);
    return v;
}
__device__ __forceinline__ float warp_reduce_max(float v) {
    v = fmaxf(v, __shfl_xor_sync(0xffffffffu, v, 16));
    v = fmaxf(v, __shfl_xor_sync(0xffffffffu, v, 8));
    v = fmaxf(v, __shfl_xor_sync(0xffffffffu, v, 4));
    v = fmaxf(v, __shfl_xor_sync(0xffffffffu, v, 2));
    v = fmaxf(v, __shfl_xor_sync(0xffffffffu, v, 1));
    return v;
}

// ---------------- A1: attention logits -------------------------------------
__global__ void k_attn_logits(const int* __restrict__ x,
                              const float* __restrict__ emb_W,
                              const float* __restrict__ h,
                              const float* __restrict__ attn_W,
                              const float* __restrict__ attn_b) {
    int l = blockIdx.x;
    int t = threadIdx.x;
    const float4* emb4 = (const float4*)(emb_W + (long)x[0] * H);
    const float4* h4   = (const float4*)h;
    const float4* wA   = (const float4*)(attn_W + (long)l * 2 * H);        // vs h0
    const float4* wB   = wA + H4;                                          // vs emb
    float acc = 0.f;
#pragma unroll 4
    for (int i = t; i < H4; i += 128) {
        float4 a = __ldg(wA + i), va = __ldg(h4 + i);
        float4 b = __ldg(wB + i), vb = __ldg(emb4 + i);
        acc = fmaf(a.x, va.x, acc); acc = fmaf(a.y, va.y, acc);
        acc = fmaf(a.z, va.z, acc); acc = fmaf(a.w, va.w, acc);
        acc = fmaf(b.x, vb.x, acc); acc = fmaf(b.y, vb.y, acc);
        acc = fmaf(b.z, vb.z, acc); acc = fmaf(b.w, vb.w, acc);
    }
    __shared__ float s[4];
    acc = warp_reduce_add(acc);
    if ((t & 31) == 0) s[t >> 5] = acc;
    __syncthreads();
    if (t == 0)
        g_attn_logits[l] = s[0] + s[1] + s[2] + s[3] + __ldg(attn_b + l);
}

// ---------------- A2: softmax (recomputed per block) + attn_applied ---------
__global__ void k_attn_apply(const float* __restrict__ enc,
                             float* __restrict__ out_attn) {
    __shared__ float w[LL];
    __shared__ float red[8];
    int t = threadIdx.x;

    float v = (t < LL) ? g_attn_logits[t] : -INFINITY;
    float m = warp_reduce_max(v);
    if ((t & 31) == 0) red[t >> 5] = m;
    __syncthreads();
    float blockmax = fmaxf(fmaxf(red[0], red[1]), fmaxf(red[2], red[3]));
    float e = (t < LL) ? expf(v - blockmax) : 0.f;
    float s = warp_reduce_add(e);
    __syncthreads();
    if ((t & 31) == 0) red[t >> 5] = s;
    __syncthreads();
    float blocksum = red[0] + red[1] + red[2] + red[3];
    if (t < LL) {
        float wt = e / blocksum;
        w[t] = wt;
        if (blockIdx.x == 0) out_attn[t] = wt;
    }
    __syncthreads();

    int k = blockIdx.x * blockDim.x + t;
    if (k < H) {
        float acc = 0.f;
#pragma unroll 8
        for (int l = 0; l < LL; ++l)
            acc = fmaf(w[l], __ldg(enc + (long)l * H + k), acc);
        g_attn_applied[k] = acc;
    }
}

// ---------------- B1: emb-half of combine (depends only on x) ---------------
// Stream 3, forked at t=0: partial[row] = comb_W[row, 0:H] . emb
__global__ void k_comb_emb(const int* __restrict__ x,
                           const float* __restrict__ emb_W,
                           const float* __restrict__ comb_W) {
    __shared__ float4 vec[H4];               // 8 KB: emb
    int t = threadIdx.x;
    const float4* emb4 = (const float4*)(emb_W + (long)x[0] * H);
    for (int i = t; i < H4; i += 256) vec[i] = __ldg(emb4 + i);
    __syncthreads();

    int warp = t >> 5, lane = t & 31;
    int row = blockIdx.x * 8 + warp;
    const float4* w = (const float4*)(comb_W + (long)row * 2 * H);   // first half
    float acc = 0.f;
#pragma unroll 8
    for (int i = lane; i < H4; i += 32) {
        float4 a = __ldcs(w + i);
        float4 v = vec[i];
        acc = fmaf(a.x, v.x, acc);
        acc = fmaf(a.y, v.y, acc);
        acc = fmaf(a.z, v.z, acc);
        acc = fmaf(a.w, v.w, acc);
    }
    acc = warp_reduce_add(acc);
    if (lane == 0) g_comb_emb[row] = acc;
}

// ---------------- B2: attn-half of combine + merge + ReLU -------------------
// lstm_in[row] = relu(partial_emb + comb_W[row, H:2H] . attn_applied + b)
__global__ void k_combine_b(const float* __restrict__ comb_W,
                            const float* __restrict__ comb_b) {
    __shared__ float4 vec[H4];               // 8 KB: attn_applied
    int t = threadIdx.x;
    const float4* ap4 = (const float4*)g_attn_applied;
    for (int i = t; i < H4; i += 256) vec[i] = ap4[i];
    __syncthreads();

    int warp = t >> 5, lane = t & 31;
    int row = blockIdx.x * 8 + warp;
    const float4* w = (const float4*)(comb_W + (long)row * 2 * H) + H4;  // second half
    float acc = 0.f;
#pragma unroll 8
    for (int i = lane; i < H4; i += 32) {
        float4 a = __ldcs(w + i);
        float4 v = vec[i];
        acc = fmaf(a.x, v.x, acc);
        acc = fmaf(a.y, v.y, acc);
        acc = fmaf(a.z, v.z, acc);
        acc = fmaf(a.w, v.w, acc);
    }
    acc = warp_reduce_add(acc);
    if (lane == 0)
        g_lstm_in[row] = fmaxf(acc + g_comb_emb[row] + __ldg(comb_b + row), 0.f);
}

// ---------------- C1b: W_hh gate partials (depends ONLY on input h) ---------
// Second stream, overlapped with the attention/combine chain AND k_wih.
__global__ void k_whh(const float* __restrict__ h,
                      const float* __restrict__ W_hh,
                      const float* __restrict__ b_hh) {
    __shared__ float4 vec[H4];               // 8 KB
    int t = threadIdx.x;
    const float4* vsrc = (const float4*)h;
    for (int i = t; i < H4; i += 256) vec[i] = __ldg(vsrc + i);
    __syncthreads();

    int warp = t >> 5, lane = t & 31;
    int row = blockIdx.x * 8 + warp;               // 0..8191
    const float4* w = (const float4*)(W_hh + (long)row * H);
    float acc = 0.f;
#pragma unroll 8
    for (int i = lane; i < H4; i += 32) {
        float4 a = __ldcs(w + i);
        float4 v = vec[i];
        acc = fmaf(a.x, v.x, acc);
        acc = fmaf(a.y, v.y, acc);
        acc = fmaf(a.z, v.z, acc);
        acc = fmaf(a.w, v.w, acc);
    }
    acc = warp_reduce_add(acc);
    if (lane == 0)
        g_gp[G4H + row] = acc + __ldg(b_hh + row);
}

// ---------------- C1a: W_ih gate partials (depends on lstm_in) --------------
__global__ void k_wih(const float* __restrict__ W_ih,
                      const float* __restrict__ b_ih) {
    __shared__ float4 vec[H4];               // 8 KB
    int t = threadIdx.x;
    const float4* vsrc = (const float4*)g_lstm_in;
    for (int i = t; i < H4; i += 256) vec[i] = vsrc[i];
    __syncthreads();

    int warp = t >> 5, lane = t & 31;
    int row = blockIdx.x * 8 + warp;               // 0..8191
    const float4* w = (const float4*)(W_ih + (long)row * H);
    float acc = 0.f;
#pragma unroll 8
    for (int i = lane; i < H4; i += 32) {
        float4 a = __ldcs(w + i);
        float4 v = vec[i];
        acc = fmaf(a.x, v.x, acc);
        acc = fmaf(a.y, v.y, acc);
        acc = fmaf(a.z, v.z, acc);
        acc = fmaf(a.w, v.w, acc);
    }
    acc = warp_reduce_add(acc);
    if (lane == 0)
        g_gp[row] = acc + __ldg(b_ih + row);
}

// ---------------- C2: LSTM cell elementwise (merges partials) ---------------
__global__ void k_cell(const float* __restrict__ c) {
    int j = blockIdx.x * blockDim.x + threadIdx.x;
    if (j < H) {
        float gi = g_gp[j]         + g_gp[G4H + j];
        float gf = g_gp[H + j]     + g_gp[G4H + H + j];
        float gg = g_gp[2 * H + j] + g_gp[G4H + 2 * H + j];
        float go = g_gp[3 * H + j] + g_gp[G4H + 3 * H + j];
        float si = 1.f / (1.f + expf(-gi));
        float sf = 1.f / (1.f + expf(-gf));
        float so = 1.f / (1.f + expf(-go));
        float cn = sf * __ldg(c + j) + si * tanhf(gg);
        g_h_new[j] = so * tanhf(cn);
    }
}

// ---------------- D: output projection (dominant GEMV) ----------------------
// 512 threads = 16 warps, 16 rows per block.
__global__ void k_logits(const float* __restrict__ out_W,
                         const float* __restrict__ out_b) {
    __shared__ float4 vec[H4];               // 8 KB
    int t = threadIdx.x;
    const float4* hv = (const float4*)g_h_new;
    for (int i = t; i < H4; i += 512) vec[i] = hv[i];
    __syncthreads();

    int warp = t >> 5, lane = t & 31;
    int row = blockIdx.x * 16 + warp;
    if (row < V) {
        const float4* w = (const float4*)(out_W + (long)row * H);
        float acc = 0.f;
#pragma unroll 8
        for (int i = lane; i < H4; i += 32) {
            float4 a = __ldcs(w + i);
            float4 v = vec[i];
            acc = fmaf(a.x, v.x, acc);
            acc = fmaf(a.y, v.y, acc);
            acc = fmaf(a.z, v.z, acc);
            acc = fmaf(a.w, v.w, acc);
        }
        acc = warp_reduce_add(acc);
        if (lane == 0) g_logits[row] = acc + __ldg(out_b + row);
    }
}

// ---------------- E1: per-block local max + sum exp(x - local max) ----------
__global__ void k_red_partial() {                 // NRED blocks x 256
    int t = threadIdx.x;
    float m = -INFINITY;
    for (int i = blockIdx.x * 256 + t; i < V; i += NRED * 256)
        m = fmaxf(m, g_logits[i]);
    float wm = warp_reduce_max(m);
    __shared__ float sm[8];
    if ((t & 31) == 0) sm[t >> 5] = wm;
    __syncthreads();
    float bm = sm[0];
#pragma unroll
    for (int i = 1; i < 8; ++i) bm = fmaxf(bm, sm[i]);

    float s = 0.f;
    for (int i = blockIdx.x * 256 + t; i < V; i += NRED * 256)
        s += expf(g_logits[i] - bm);
    float ws = warp_reduce_add(s);
    __syncthreads();
    if ((t & 31) == 0) sm[t >> 5] = ws;
    __syncthreads();
    if (t == 0) {
        float r = 0.f;
#pragma unroll
        for (int i = 0; i < 8; ++i) r += sm[i];
        g_pmax[blockIdx.x] = bm;
        g_psum[blockIdx.x] = r;
    }
}

// ---------------- E2: merge partials (per block) + write logp ---------------
__global__ void k_write_logp(float* __restrict__ out) {   // grid covers V, 256 thr
    __shared__ float s_shift;
    int t = threadIdx.x;
    if (t < 32) {
        float mm = fmaxf(g_pmax[t], g_pmax[t + 32]);
        mm = warp_reduce_max(mm);
        float ss = g_psum[t] * expf(g_pmax[t] - mm)
                 + g_psum[t + 32] * expf(g_pmax[t + 32] - mm);
        ss = warp_reduce_add(ss);
        if (t == 0) s_shift = mm + logf(ss);
    }
    __syncthreads();
    float shift = s_shift;
    int i = blockIdx.x * blockDim.x + t;
    if (i < V) out[i] = g_logits[i] - shift;
}

// ---------------- launch -----------------------------------------------------
extern "C" void kernel_launch(void* const* d_in, const int* in_sizes, int n_in,
                              void* d_out, int out_size) {
    const int*   x      = (const int*)  d_in[0];
    const float* enc    = (const float*)d_in[1];
    const float* h      = (const float*)d_in[2];
    const float* c      = (const float*)d_in[3];
    const float* emb_W  = (const float*)d_in[4];
    const float* attn_W = (const float*)d_in[5];
    const float* attn_b = (const float*)d_in[6];
    const float* comb_W = (const float*)d_in[7];
    const float* comb_b = (const float*)d_in[8];
    const float* W_ih   = (const float*)d_in[9];
    const float* W_hh   = (const float*)d_in[10];
    const float* b_ih   = (const float*)d_in[11];
    const float* b_hh   = (const float*)d_in[12];
    const float* out_W  = (const float*)d_in[13];
    const float* out_b  = (const float*)d_in[14];
    float* out = (float*)d_out;

    // Forks: W_hh GEMV (needs only h) on s2; emb-half of combine (needs only x)
    // on s3. Both overlap the attention chain on the main stream.
    cudaEventRecord(g_ev_fork, 0);
    cudaStreamWaitEvent(g_s2, g_ev_fork, 0);
    k_whh<<<GB, 256, 0, g_s2>>>(h, W_hh, b_hh);
    cudaEventRecord(g_ev_join, g_s2);

    cudaStreamWaitEvent(g_s3, g_ev_fork, 0);
    k_comb_emb<<<H / 8, 256, 0, g_s3>>>(x, emb_W, comb_W);
    cudaEventRecord(g_ev_comb, g_s3);

    // Main-stream dependency chain.
    k_attn_logits<<<LL, 128>>>(x, emb_W, h, attn_W, attn_b);
    k_attn_apply<<<H / 256, 256>>>(enc, out + V);
    cudaStreamWaitEvent(0, g_ev_comb, 0);
    k_combine_b<<<H / 8, 256>>>(comb_W, comb_b);
    k_wih<<<GB, 256>>>(W_ih, b_ih);

    // Join before the cell combines both gate partials.
    cudaStreamWaitEvent(0, g_ev_join, 0);
    k_cell<<<(H + 255) / 256, 256>>>(c);
    k_logits<<<(V + 15) / 16, 512>>>(out_W, out_b);
    k_red_partial<<<NRED, 256>>>();
    k_write_logp<<<(V + 255) / 256, 256>>>(out);
}

// round 16
// speedup vs baseline: 1.0312x; 1.0312x over previous
#include <cuda_runtime.h>
#include <math.h>

#define H    2048
#define V    50257
#define LL   80
#define H4   (H/4)      // 512 float4 per H-length vector
#define G4H  (4*H)      // 8192 gate rows per matrix
#define GB   (G4H / 8)  // 1024 blocks per gate matrix
#define NRED 64         // partial-reduction blocks for log-softmax

// ---------------- scratch (device globals — no allocation allowed) ----------
__device__ float g_attn_logits[LL];
__device__ float g_attn_applied[H];
__device__ float g_comb_emb[H];    // emb-half partial of the combine GEMV
__device__ float g_lstm_in[H];
__device__ float g_gp[2 * G4H];    // [0,4H): W_ih partial + b_ih ; [4H,8H): W_hh partial + b_hh
__device__ float g_h_new[H];
__device__ float g_logits[V];
__device__ float g_pmax[NRED];
__device__ float g_psum[NRED];

// ---------------- streams/events (static init; no device alloc in launch) ---
static cudaStream_t g_s2, g_s3;
static cudaEvent_t  g_ev_fork, g_ev_join, g_ev_comb;
namespace {
struct StreamInit {
    StreamInit() {
        cudaStreamCreateWithFlags(&g_s2, cudaStreamNonBlocking);
        cudaStreamCreateWithFlags(&g_s3, cudaStreamNonBlocking);
        cudaEventCreateWithFlags(&g_ev_fork, cudaEventDisableTiming);
        cudaEventCreateWithFlags(&g_ev_join, cudaEventDisableTiming);
        cudaEventCreateWithFlags(&g_ev_comb, cudaEventDisableTiming);
    }
};
StreamInit g_stream_init;
}

// ---------------- helpers ----------------
__device__ __forceinline__ float warp_reduce_add(float v) {
    v += __shfl_xor_sync(0xffffffffu, v, 16);
    v += __shfl_xor_sync(0xffffffffu, v, 8);
    v += __shfl_xor_sync(0xffffffffu, v, 4);
    v += __shfl_xor_sync(0xffffffffu, v, 2);
    v += __shfl_xor_sync(0xffffffffu, v, 1);
    return v;
}
__device__ __forceinline__ float warp_reduce_max(float v) {
    v = fmaxf(v, __shfl_xor_sync(0xffffffffu, v, 16));
    v = fmaxf(v, __shfl_xor_sync(0xffffffffu, v, 8));
    v = fmaxf(v, __shfl_xor_sync(0xffffffffu, v, 4));
    v = fmaxf(v, __shfl_xor_sync(0xffffffffu, v, 2));
    v = fmaxf(v, __shfl_xor_sync(0xffffffffu, v, 1));
    return v;
}

// ---------------- A1: attention logits -------------------------------------
__global__ void k_attn_logits(const int* __restrict__ x,
                              const float* __restrict__ emb_W,
                              const float* __restrict__ h,
                              const float* __restrict__ attn_W,
                              const float* __restrict__ attn_b) {
    int l = blockIdx.x;
    int t = threadIdx.x;
    const float4* emb4 = (const float4*)(emb_W + (long)x[0] * H);
    const float4* h4   = (const float4*)h;
    const float4* wA   = (const float4*)(attn_W + (long)l * 2 * H);        // vs h0
    const float4* wB   = wA + H4;                                          // vs emb
    float acc = 0.f;
#pragma unroll 4
    for (int i = t; i < H4; i += 128) {
        float4 a = __ldg(wA + i), va = __ldg(h4 + i);
        float4 b = __ldg(wB + i), vb = __ldg(emb4 + i);
        acc = fmaf(a.x, va.x, acc); acc = fmaf(a.y, va.y, acc);
        acc = fmaf(a.z, va.z, acc); acc = fmaf(a.w, va.w, acc);
        acc = fmaf(b.x, vb.x, acc); acc = fmaf(b.y, vb.y, acc);
        acc = fmaf(b.z, vb.z, acc); acc = fmaf(b.w, vb.w, acc);
    }
    __shared__ float s[4];
    acc = warp_reduce_add(acc);
    if ((t & 31) == 0) s[t >> 5] = acc;
    __syncthreads();
    if (t == 0)
        g_attn_logits[l] = s[0] + s[1] + s[2] + s[3] + __ldg(attn_b + l);
}

// ---------------- A2: softmax (recomputed per block) + attn_applied ---------
// grid = 64 blocks x 256 threads: each block owns 32 columns; threads are
// (col 0..31) x (lgroup 0..7), each thread sums 10 L-terms -> smem reduce.
__global__ void k_attn_apply(const float* __restrict__ enc,
                             float* __restrict__ out_attn) {
    __shared__ float w[LL];
    __shared__ float red[8];
    __shared__ float part[8][33];            // +1 pad avoids bank conflicts
    int t = threadIdx.x;

    // softmax over the 80 logits (warps 4..7 contribute identity values)
    float v = (t < LL) ? g_attn_logits[t] : -INFINITY;
    float m = warp_reduce_max(v);
    if ((t & 31) == 0) red[t >> 5] = m;
    __syncthreads();
    float blockmax = fmaxf(fmaxf(red[0], red[1]), fmaxf(red[2], red[3]));
    float e = (t < LL) ? expf(v - blockmax) : 0.f;
    float s = warp_reduce_add(e);
    __syncthreads();
    if ((t & 31) == 0) red[t >> 5] = s;
    __syncthreads();
    float blocksum = red[0] + red[1] + red[2] + red[3];
    if (t < LL) {
        float wt = e / blocksum;
        w[t] = wt;
        if (blockIdx.x == 0) out_attn[t] = wt;
    }
    __syncthreads();

    int colloc = t & 31;                     // 0..31
    int lgroup = t >> 5;                     // 0..7 (10 L each)
    int col = blockIdx.x * 32 + colloc;
    float acc = 0.f;
#pragma unroll
    for (int j = 0; j < 10; ++j) {
        int l = lgroup * 10 + j;
        acc = fmaf(w[l], __ldg(enc + (long)l * H + col), acc);
    }
    part[lgroup][colloc] = acc;
    __syncthreads();
    if (t < 32) {
        float sum = part[0][t];
#pragma unroll
        for (int g = 1; g < 8; ++g) sum += part[g][t];
        g_attn_applied[blockIdx.x * 32 + t] = sum;
    }
}

// ---------------- B1: emb-half of combine (depends only on x) ---------------
// Stream 3, forked at t=0: partial[row] = comb_W[row, 0:H] . emb
__global__ void k_comb_emb(const int* __restrict__ x,
                           const float* __restrict__ emb_W,
                           const float* __restrict__ comb_W) {
    __shared__ float4 vec[H4];               // 8 KB: emb
    int t = threadIdx.x;
    const float4* emb4 = (const float4*)(emb_W + (long)x[0] * H);
    for (int i = t; i < H4; i += 256) vec[i] = __ldg(emb4 + i);
    __syncthreads();

    int warp = t >> 5, lane = t & 31;
    int row = blockIdx.x * 8 + warp;
    const float4* w = (const float4*)(comb_W + (long)row * 2 * H);   // first half
    float acc = 0.f;
#pragma unroll 8
    for (int i = lane; i < H4; i += 32) {
        float4 a = __ldcs(w + i);
        float4 v = vec[i];
        acc = fmaf(a.x, v.x, acc);
        acc = fmaf(a.y, v.y, acc);
        acc = fmaf(a.z, v.z, acc);
        acc = fmaf(a.w, v.w, acc);
    }
    acc = warp_reduce_add(acc);
    if (lane == 0) g_comb_emb[row] = acc;
}

// ---------------- B2: attn-half of combine + merge + ReLU -------------------
// lstm_in[row] = relu(partial_emb + comb_W[row, H:2H] . attn_applied + b)
__global__ void k_combine_b(const float* __restrict__ comb_W,
                            const float* __restrict__ comb_b) {
    __shared__ float4 vec[H4];               // 8 KB: attn_applied
    int t = threadIdx.x;
    const float4* ap4 = (const float4*)g_attn_applied;
    for (int i = t; i < H4; i += 256) vec[i] = ap4[i];
    __syncthreads();

    int warp = t >> 5, lane = t & 31;
    int row = blockIdx.x * 8 + warp;
    const float4* w = (const float4*)(comb_W + (long)row * 2 * H) + H4;  // second half
    float acc = 0.f;
#pragma unroll 8
    for (int i = lane; i < H4; i += 32) {
        float4 a = __ldcs(w + i);
        float4 v = vec[i];
        acc = fmaf(a.x, v.x, acc);
        acc = fmaf(a.y, v.y, acc);
        acc = fmaf(a.z, v.z, acc);
        acc = fmaf(a.w, v.w, acc);
    }
    acc = warp_reduce_add(acc);
    if (lane == 0)
        g_lstm_in[row] = fmaxf(acc + g_comb_emb[row] + __ldg(comb_b + row), 0.f);
}

// ---------------- C1b: W_hh gate partials (depends ONLY on input h) ---------
__global__ void k_whh(const float* __restrict__ h,
                      const float* __restrict__ W_hh,
                      const float* __restrict__ b_hh) {
    __shared__ float4 vec[H4];               // 8 KB
    int t = threadIdx.x;
    const float4* vsrc = (const float4*)h;
    for (int i = t; i < H4; i += 256) vec[i] = __ldg(vsrc + i);
    __syncthreads();

    int warp = t >> 5, lane = t & 31;
    int row = blockIdx.x * 8 + warp;               // 0..8191
    const float4* w = (const float4*)(W_hh + (long)row * H);
    float acc = 0.f;
#pragma unroll 8
    for (int i = lane; i < H4; i += 32) {
        float4 a = __ldcs(w + i);
        float4 v = vec[i];
        acc = fmaf(a.x, v.x, acc);
        acc = fmaf(a.y, v.y, acc);
        acc = fmaf(a.z, v.z, acc);
        acc = fmaf(a.w, v.w, acc);
    }
    acc = warp_reduce_add(acc);
    if (lane == 0)
        g_gp[G4H + row] = acc + __ldg(b_hh + row);
}

// ---------------- C1a: W_ih gate partials (depends on lstm_in) --------------
__global__ void k_wih(const float* __restrict__ W_ih,
                      const float* __restrict__ b_ih) {
    __shared__ float4 vec[H4];               // 8 KB
    int t = threadIdx.x;
    const float4* vsrc = (const float4*)g_lstm_in;
    for (int i = t; i < H4; i += 256) vec[i] = vsrc[i];
    __syncthreads();

    int warp = t >> 5, lane = t & 31;
    int row = blockIdx.x * 8 + warp;               // 0..8191
    const float4* w = (const float4*)(W_ih + (long)row * H);
    float acc = 0.f;
#pragma unroll 8
    for (int i = lane; i < H4; i += 32) {
        float4 a = __ldcs(w + i);
        float4 v = vec[i];
        acc = fmaf(a.x, v.x, acc);
        acc = fmaf(a.y, v.y, acc);
        acc = fmaf(a.z, v.z, acc);
        acc = fmaf(a.w, v.w, acc);
    }
    acc = warp_reduce_add(acc);
    if (lane == 0)
        g_gp[row] = acc + __ldg(b_ih + row);
}

// ---------------- C2: LSTM cell elementwise (merges partials) ---------------
__global__ void k_cell(const float* __restrict__ c) {
    int j = blockIdx.x * blockDim.x + threadIdx.x;
    if (j < H) {
        float gi = g_gp[j]         + g_gp[G4H + j];
        float gf = g_gp[H + j]     + g_gp[G4H + H + j];
        float gg = g_gp[2 * H + j] + g_gp[G4H + 2 * H + j];
        float go = g_gp[3 * H + j] + g_gp[G4H + 3 * H + j];
        float si = 1.f / (1.f + expf(-gi));
        float sf = 1.f / (1.f + expf(-gf));
        float so = 1.f / (1.f + expf(-go));
        float cn = sf * __ldg(c + j) + si * tanhf(gg);
        g_h_new[j] = so * tanhf(cn);
    }
}

// ---------------- D: output projection (dominant GEMV) ----------------------
// 512 threads = 16 warps, 16 rows per block.
__global__ void k_logits(const float* __restrict__ out_W,
                         const float* __restrict__ out_b) {
    __shared__ float4 vec[H4];               // 8 KB
    int t = threadIdx.x;
    const float4* hv = (const float4*)g_h_new;
    for (int i = t; i < H4; i += 512) vec[i] = hv[i];
    __syncthreads();

    int warp = t >> 5, lane = t & 31;
    int row = blockIdx.x * 16 + warp;
    if (row < V) {
        const float4* w = (const float4*)(out_W + (long)row * H);
        float acc = 0.f;
#pragma unroll 8
        for (int i = lane; i < H4; i += 32) {
            float4 a = __ldcs(w + i);
            float4 v = vec[i];
            acc = fmaf(a.x, v.x, acc);
            acc = fmaf(a.y, v.y, acc);
            acc = fmaf(a.z, v.z, acc);
            acc = fmaf(a.w, v.w, acc);
        }
        acc = warp_reduce_add(acc);
        if (lane == 0) g_logits[row] = acc + __ldg(out_b + row);
    }
}

// ---------------- E1: per-block local max + sum exp(x - local max) ----------
__global__ void k_red_partial() {                 // NRED blocks x 256
    int t = threadIdx.x;
    float m = -INFINITY;
    for (int i = blockIdx.x * 256 + t; i < V; i += NRED * 256)
        m = fmaxf(m, g_logits[i]);
    float wm = warp_reduce_max(m);
    __shared__ float sm[8];
    if ((t & 31) == 0) sm[t >> 5] = wm;
    __syncthreads();
    float bm = sm[0];
#pragma unroll
    for (int i = 1; i < 8; ++i) bm = fmaxf(bm, sm[i]);

    float s = 0.f;
    for (int i = blockIdx.x * 256 + t; i < V; i += NRED * 256)
        s += expf(g_logits[i] - bm);
    float ws = warp_reduce_add(s);
    __syncthreads();
    if ((t & 31) == 0) sm[t >> 5] = ws;
    __syncthreads();
    if (t == 0) {
        float r = 0.f;
#pragma unroll
        for (int i = 0; i < 8; ++i) r += sm[i];
        g_pmax[blockIdx.x] = bm;
        g_psum[blockIdx.x] = r;
    }
}

// ---------------- E2: merge partials (per block) + write logp ---------------
__global__ void k_write_logp(float* __restrict__ out) {   // grid covers V, 256 thr
    __shared__ float s_shift;
    int t = threadIdx.x;
    if (t < 32) {
        float mm = fmaxf(g_pmax[t], g_pmax[t + 32]);
        mm = warp_reduce_max(mm);
        float ss = g_psum[t] * expf(g_pmax[t] - mm)
                 + g_psum[t + 32] * expf(g_pmax[t + 32] - mm);
        ss = warp_reduce_add(ss);
        if (t == 0) s_shift = mm + logf(ss);
    }
    __syncthreads();
    float shift = s_shift;
    int i = blockIdx.x * blockDim.x + t;
    if (i < V) out[i] = g_logits[i] - shift;
}

// ---------------- launch -----------------------------------------------------
extern "C" void kernel_launch(void* const* d_in, const int* in_sizes, int n_in,
                              void* d_out, int out_size) {
    const int*   x      = (const int*)  d_in[0];
    const float* enc    = (const float*)d_in[1];
    const float* h      = (const float*)d_in[2];
    const float* c      = (const float*)d_in[3];
    const float* emb_W  = (const float*)d_in[4];
    const float* attn_W = (const float*)d_in[5];
    const float* attn_b = (const float*)d_in[6];
    const float* comb_W = (const float*)d_in[7];
    const float* comb_b = (const float*)d_in[8];
    const float* W_ih   = (const float*)d_in[9];
    const float* W_hh   = (const float*)d_in[10];
    const float* b_ih   = (const float*)d_in[11];
    const float* b_hh   = (const float*)d_in[12];
    const float* out_W  = (const float*)d_in[13];
    const float* out_b  = (const float*)d_in[14];
    float* out = (float*)d_out;

    // Forks: W_hh GEMV (needs only h) on s2; emb-half of combine (needs only x)
    // on s3. Both overlap the attention chain on the main stream.
    cudaEventRecord(g_ev_fork, 0);
    cudaStreamWaitEvent(g_s2, g_ev_fork, 0);
    k_whh<<<GB, 256, 0, g_s2>>>(h, W_hh, b_hh);
    cudaEventRecord(g_ev_join, g_s2);

    cudaStreamWaitEvent(g_s3, g_ev_fork, 0);
    k_comb_emb<<<H / 8, 256, 0, g_s3>>>(x, emb_W, comb_W);
    cudaEventRecord(g_ev_comb, g_s3);

    // Main-stream dependency chain.
    k_attn_logits<<<LL, 128>>>(x, emb_W, h, attn_W, attn_b);
    k_attn_apply<<<H / 32, 256>>>(enc, out + V);
    cudaStreamWaitEvent(0, g_ev_comb, 0);
    k_combine_b<<<H / 8, 256>>>(comb_W, comb_b);
    k_wih<<<GB, 256>>>(W_ih, b_ih);

    // Join before the cell combines both gate partials.
    cudaStreamWaitEvent(0, g_ev_join, 0);
    k_cell<<<(H + 255) / 256, 256>>>(c);
    k_logits<<<(V + 15) / 16, 512>>>(out_W, out_b);
    k_red_partial<<<NRED, 256>>>();
    k_write_logp<<<(V + 255) / 256, 256>>>(out);
}